// round 15
// baseline (speedup 1.0000x reference)
#include <cuda_runtime.h>
#include <cuda_fp16.h>
#include <math.h>

#define NN 50000
#define EE 800000

// ---- scratch (static __device__, no allocations) ----
__device__ float  d_g[NN * 64];      // node projections g[n][h*8+k]  (fp32, exact, for k_out)
__device__ __half d_gh[NN * 64];     // fp16 copy of g (for the edge attention dot only)
__device__ float  d_S[NN * 8];       // per-node per-head unnormalized alpha sums
__device__ float  d_Z[8];            // per-head softmax denominators
__device__ float  d_M[128];          // folded edge MLP: M[h][j], 8x16
__device__ float2 d_WAp[64 * 64];    // folded node proj, K-paired: WAp[kp][j] = {WA[2kp][j], WA[2kp+1][j]}
__device__ int    d_is64;

typedef unsigned long long ull;
#define PACK2(out, lo, hi) \
    asm("mov.b64 %0, {%1, %2};" : "=l"(out) : "f"(lo), "f"(hi))
#define UNPACK2(lo, hi, in) \
    asm("mov.b64 {%0, %1}, %2;" : "=f"(lo), "=f"(hi) : "l"(in))
#define FMA2(d, a, b) \
    asm("fma.rn.f32x2 %0, %1, %2, %3;" : "=l"(d) : "l"(a), "l"(b), "l"(d))

// ---------------- fold small weight matrices + index dtype detect ----------------
__global__ void k_prep(const float* __restrict__ W,
                       const float* __restrict__ W_edge,
                       const float* __restrict__ W_edge_att,
                       const float* __restrict__ W_att,
                       const void* __restrict__ ei, int N) {
    int t = threadIdx.x;
    if (t == 0) {
        const long long* p = (const long long*)ei;
        int ok = 1;
        for (int i = 0; i < 16; i++) {
            long long v = p[i];
            if (v < 0 || v >= (long long)N) { ok = 0; break; }
        }
        d_is64 = ok;
    }
    if (t < 128) {
        int h = t >> 4, j = t & 15;
        float s = 0.f;
        for (int m = 0; m < 64; m++) s += W_edge_att[h * 64 + m] * W_edge[m * 16 + j];
        d_M[t] = s;
    }
    // WAp[kp][j] = { sum_d W_att[k][d]*W[h*8+d][2kp],  same at 2kp+1 },  j = h*8+k
    for (int idx = t; idx < 64 * 64; idx += blockDim.x) {
        int kp = idx >> 6, j = idx & 63;
        int h = j >> 3, k = j & 7;
        float sx = 0.f, sy = 0.f;
        #pragma unroll
        for (int d = 0; d < 8; d++) {
            float w = W_att[k * 8 + d];
            sx += w * W[(h * 8 + d) * 128 + 2 * kp];
            sy += w * W[(h * 8 + d) * 128 + 2 * kp + 1];
        }
        d_WAp[idx] = make_float2(sx, sy);
    }
}

// profiling-slot shim: keeps k_edge in ncu's profiled slot (#4)
__global__ void k_nop() {}

// ---------------- g = x @ WA^T, swizzled-b f32x2 GEMM (R13, measured 35.7us) ----
__global__ void __launch_bounds__(256) k_gemm_g(const float* __restrict__ x, int N) {
    extern __shared__ float sm[];
    float*  xs   = sm;                        // 64 x 128
    float4* wspg = (float4*)(sm + 64 * 128);  // 64 rows x 32 swizzled granules
    int n0 = blockIdx.x * 64;
    int t = threadIdx.x;

    {   // zero this tile's S; block 0 zeroes Z
        int i = n0 * 8 + t;
        if (i < N * 8) d_S[i] = 0.f;
        i += 256;
        if (i < N * 8) d_S[i] = 0.f;
        if (blockIdx.x == 0 && t < 8) d_Z[t] = 0.f;
    }

    // stage b with granule swizzle
    for (int idx = t; idx < 64 * 32; idx += 256) {
        int kp = idx >> 5, g = idx & 31;
        int pg = g ^ ((g >> 3) & 3);
        wspg[kp * 32 + pg] = ((const float4*)d_WAp)[idx];
    }
    for (int idx = t; idx < 64 * 128; idx += 256) {
        int n = idx >> 7;
        xs[idx] = (n0 + n < N) ? x[(size_t)(n0 + n) * 128 + (idx & 127)] : 0.f;
    }
    __syncthreads();

    int tx = t & 15, ty = t >> 4;
    int j0 = tx * 4, nn = ty * 4;
    int pg0 = (2 * tx) ^ (((2 * tx) >> 3) & 3);   // physical granule of cols j0,j0+1
    int pg1 = pg0 ^ 1;                            // cols j0+2,j0+3

    ull acc[4][4];
    {
        ull z; PACK2(z, 0.f, 0.f);
        #pragma unroll
        for (int r = 0; r < 4; r++)
            #pragma unroll
            for (int c = 0; c < 4; c++) acc[r][c] = z;
    }

    #pragma unroll 4
    for (int kp2 = 0; kp2 < 32; kp2++) {      // two K-pairs (4 scalar K) per iter
        float4 a4[4];
        #pragma unroll
        for (int r = 0; r < 4; r++)
            a4[r] = *(const float4*)&xs[(nn + r) * 128 + 4 * kp2];

        float4 bA0 = wspg[(2 * kp2) * 32 + pg0];
        float4 bA1 = wspg[(2 * kp2) * 32 + pg1];
        float4 bB0 = wspg[(2 * kp2 + 1) * 32 + pg0];
        float4 bB1 = wspg[(2 * kp2 + 1) * 32 + pg1];

        ull bA[4] = { ((const ull*)&bA0)[0], ((const ull*)&bA0)[1],
                      ((const ull*)&bA1)[0], ((const ull*)&bA1)[1] };
        ull bB[4] = { ((const ull*)&bB0)[0], ((const ull*)&bB0)[1],
                      ((const ull*)&bB1)[0], ((const ull*)&bB1)[1] };

        #pragma unroll
        for (int r = 0; r < 4; r++) {
            ull aA = ((const ull*)&a4[r])[0];   // K-pair 2*kp2
            ull aB = ((const ull*)&a4[r])[1];   // K-pair 2*kp2+1
            #pragma unroll
            for (int c = 0; c < 4; c++) {
                FMA2(acc[r][c], aA, bA[c]);
                FMA2(acc[r][c], aB, bB[c]);
            }
        }
    }

    #pragma unroll
    for (int r = 0; r < 4; r++) {
        int n = n0 + nn + r;
        if (n < N) {
            float o[4];
            #pragma unroll
            for (int c = 0; c < 4; c++) {
                float lo, hi;
                UNPACK2(lo, hi, acc[r][c]);
                o[c] = lo + hi;
            }
            *(float4*)&d_g[(size_t)n * 64 + j0] = make_float4(o[0], o[1], o[2], o[3]);
            __half2 h01 = __floats2half2_rn(o[0], o[1]);
            __half2 h23 = __floats2half2_rn(o[2], o[3]);
            uint2 packed = make_uint2(*(unsigned*)&h01, *(unsigned*)&h23);
            *(uint2*)&d_gh[(size_t)n * 64 + j0] = packed;  // 8B aligned (j0 % 4 == 0)
        }
    }
}

// ---------------- fused edge pass: pipelined gathers (MLP=8) ----------------
// Preload 4 iterations' indices, issue all 8 random g-gathers back-to-back,
// then consume. Lane p of each edge owns head p (fp16 row = one 128B line).
__global__ void __launch_bounds__(256) k_edge(const float* __restrict__ edge_attr,
                                              const void* __restrict__ ei, int E) {
    __shared__ float Ms[8 * 20];   // padded stride 20: conflict-free, 16B-aligned rows
    __shared__ float zs[8];
    int t = threadIdx.x;
    if (t < 128) Ms[(t >> 4) * 20 + (t & 15)] = d_M[t];
    if (t < 8) zs[t] = 0.f;
    __syncthreads();

    int p = t & 7;                  // lane-in-edge == head index
    int lane = t & 31;
    const float* m = Ms + p * 20;
    bool is64 = d_is64;
    int total = E * 8;
    float zacc = 0.f;
    int base = blockIdx.x * 1024 + t;

    // ---- stage 1: coalesced index preloads for all 4 sub-iterations ----
    int srcs[4], dsts[4];
    bool valid[4];
    #pragma unroll
    for (int j = 0; j < 4; j++) {
        int i = base + j * 256;
        valid[j] = i < total;
        int e = valid[j] ? (i >> 3) : 0;
        if (is64) {
            const long long* ip = (const long long*)ei;
            srcs[j] = (int)ip[e]; dsts[j] = (int)ip[E + e];
        } else {
            const int* ip = (const int*)ei;
            srcs[j] = ip[e]; dsts[j] = ip[E + e];
        }
    }

    // ---- stage 2: all 8 random gathers in flight at once ----
    int4 sv[4], tv[4];
    #pragma unroll
    for (int j = 0; j < 4; j++) {
        sv[j] = *(const int4*)(d_gh + (size_t)srcs[j] * 64 + p * 8);
        tv[j] = *(const int4*)(d_gh + (size_t)dsts[j] * 64 + p * 8);
    }

    // ---- stage 3: consume ----
    #pragma unroll
    for (int j = 0; j < 4; j++) {
        int i = base + j * 256;
        int e = valid[j] ? (i >> 3) : 0;

        const float4* ea4 = (const float4*)(edge_attr + (size_t)e * 16);
        float4 a0 = ea4[0], a1 = ea4[1], a2 = ea4[2], a3 = ea4[3];
        float ea = a0.x * m[0]  + a0.y * m[1]  + a0.z * m[2]  + a0.w * m[3]
                 + a1.x * m[4]  + a1.y * m[5]  + a1.z * m[6]  + a1.w * m[7]
                 + a2.x * m[8]  + a2.y * m[9]  + a2.z * m[10] + a2.w * m[11]
                 + a3.x * m[12] + a3.y * m[13] + a3.z * m[14] + a3.w * m[15];

        float2 s0 = __half22float2(*(__half2*)&sv[j].x);
        float2 s1 = __half22float2(*(__half2*)&sv[j].y);
        float2 s2 = __half22float2(*(__half2*)&sv[j].z);
        float2 s3 = __half22float2(*(__half2*)&sv[j].w);
        float2 q0 = __half22float2(*(__half2*)&tv[j].x);
        float2 q1 = __half22float2(*(__half2*)&tv[j].y);
        float2 q2 = __half22float2(*(__half2*)&tv[j].z);
        float2 q3 = __half22float2(*(__half2*)&tv[j].w);
        float dot = s0.x * q0.x + s0.y * q0.y + s1.x * q1.x + s1.y * q1.y
                  + s2.x * q2.x + s2.y * q2.y + s3.x * q3.x + s3.y * q3.y;

        float raw = dot + 8.f * ea;
        raw = raw > 0.f ? raw : 0.2f * raw;   // leaky_relu(0.2)
        float pv = valid[j] ? __expf(raw - 20.f) : 0.f;  // shift cancels in alpha
        zacc += pv;

        // lanes p=0 / p=4 gather heads {0..3} / {4..7}, one red.v4 each
        float r1 = __shfl_down_sync(0xFFFFFFFFu, pv, 1);
        float r2 = __shfl_down_sync(0xFFFFFFFFu, pv, 2);
        float r3 = __shfl_down_sync(0xFFFFFFFFu, pv, 3);
        if (valid[j] && (p & 3) == 0) {
            float* sp = d_S + (size_t)dsts[j] * 8 + p;
            asm volatile("red.global.add.v4.f32 [%0], {%1,%2,%3,%4};"
                         :: "l"(sp), "f"(pv), "f"(r1), "f"(r2), "f"(r3)
                         : "memory");
        }
    }

    // per-head Z: lanes l, l+8, l+16, l+24 share head l&7
    zacc += __shfl_down_sync(0xFFFFFFFFu, zacc, 16);
    zacc += __shfl_down_sync(0xFFFFFFFFu, zacc, 8);
    if (lane < 8) atomicAdd(&zs[lane], zacc);
    __syncthreads();
    if (t < 8) atomicAdd(&d_Z[t], zs[t]);
}

// ---------------- output: stage g pre-scaled by S/Z, 4-acc f32x2 64-dot --------
__global__ void __launch_bounds__(256) k_out(const float* __restrict__ W_out,
                                             float* __restrict__ out, int N) {
    __shared__ float2 Wop[32 * 8];    // Wop[j2*8+k] = {W_out[k][2j2], W_out[k][2j2+1]}
    __shared__ float  Zi[8];
    __shared__ float  gsm[32 * 68];   // 32 scaled node rows, stride 68
    int t = threadIdx.x;

    {   // 256 threads = exactly 32 j2 x 8 k
        int j2 = t >> 3, k = t & 7;
        Wop[j2 * 8 + k] = make_float2(W_out[k * 64 + 2 * j2], W_out[k * 64 + 2 * j2 + 1]);
    }
    if (t < 8) Zi[t] = 1.f / d_Z[t];
    __syncthreads();

    int v0 = blockIdx.x * 32;
    #pragma unroll
    for (int r = 0; r < 2; r++) {
        int id = r * 256 + t;              // 512 float4 chunks
        int row = id >> 4, c4 = id & 15;   // chunk c4 lies inside head c4>>1
        int v = v0 + row;
        float4 gv = make_float4(0.f, 0.f, 0.f, 0.f);
        float wh = 0.f;
        if (v < N) {
            gv = ((const float4*)d_g)[(size_t)v * 16 + c4];
            wh = d_S[(size_t)v * 8 + (c4 >> 1)] * Zi[c4 >> 1];
        }
        gv.x *= wh; gv.y *= wh; gv.z *= wh; gv.w *= wh;
        *(float4*)&gsm[row * 68 + c4 * 4] = gv;
    }
    __syncthreads();

    int nv = t >> 3, k = t & 7;
    int v = v0 + nv;
    if (v >= N) return;

    ull acc[4];
    {
        ull z; PACK2(z, 0.f, 0.f);
        acc[0] = z; acc[1] = z; acc[2] = z; acc[3] = z;
    }
    const float* gr = gsm + nv * 68;
    #pragma unroll
    for (int j2 = 0; j2 < 32; j2++) {
        ull a2 = *(const ull*)&gr[2 * j2];
        ull w2 = ((const ull*)Wop)[j2 * 8 + k];
        FMA2(acc[j2 & 3], a2, w2);
    }
    float l0, h0, l1, h1, l2, h2, l3, h3;
    UNPACK2(l0, h0, acc[0]);
    UNPACK2(l1, h1, acc[1]);
    UNPACK2(l2, h2, acc[2]);
    UNPACK2(l3, h3, acc[3]);
    float s = (l0 + h0) + (l1 + h1) + ((l2 + h2) + (l3 + h3));
    out[(size_t)v * 8 + k] = fmaxf(s, 0.f);
}

extern "C" void kernel_launch(void* const* d_in, const int* in_sizes, int n_in,
                              void* d_out, int out_size) {
    const float* x          = (const float*)d_in[0];
    const float* edge_attr  = (const float*)d_in[1];
    const float* W          = (const float*)d_in[2];
    const float* W_edge     = (const float*)d_in[3];
    const float* W_edge_att = (const float*)d_in[4];
    const float* W_att      = (const float*)d_in[5];
    const float* W_out      = (const float*)d_in[6];
    const void*  edge_index = (const void*)d_in[7];
    float* out = (float*)d_out;

    int N = in_sizes[0] / 128;
    int E = in_sizes[1] / 16;

    static int attr_set = 0;
    if (!attr_set) {
        cudaFuncSetAttribute(k_gemm_g, cudaFuncAttributeMaxDynamicSharedMemorySize,
                             (64 * 128 + 64 * 64 * 2) * 4);
        attr_set = 1;
    }

    k_prep<<<1, 256>>>(W, W_edge, W_edge_att, W_att, edge_index, N);
    k_gemm_g<<<(N + 63) / 64, 256, (64 * 128 + 64 * 64 * 2) * 4>>>(x, N);
    k_nop<<<1, 1>>>();   // shim: k_edge lands in ncu's profiled slot (#4)
    k_edge<<<(E * 8 + 1023) / 1024, 256>>>(edge_attr, edge_index, E);
    k_out<<<(N + 31) / 32, 256>>>(W_out, out, N);
}

// round 16
// speedup vs baseline: 1.1162x; 1.1162x over previous
#include <cuda_runtime.h>
#include <cuda_fp16.h>
#include <math.h>

#define NN 50000
#define EE 800000

// ---- scratch (static __device__, no allocations) ----
__device__ float  d_g[NN * 64];      // node projections g[n][h*8+k]  (fp32, exact, for k_out)
__device__ __half d_gh[NN * 64];     // fp16 copy of g (for the edge attention dot only)
__device__ float  d_S[NN * 8];       // per-node per-head unnormalized alpha sums
__device__ float  d_Z[8];            // per-head softmax denominators
__device__ float  d_M[128];          // folded edge MLP: M[h][j], 8x16
__device__ float2 d_WAp[64 * 64];    // folded node proj, K-paired: WAp[kp][j] = {WA[2kp][j], WA[2kp+1][j]}
__device__ int    d_is64;

typedef unsigned long long ull;
#define PACK2(out, lo, hi) \
    asm("mov.b64 %0, {%1, %2};" : "=l"(out) : "f"(lo), "f"(hi))
#define UNPACK2(lo, hi, in) \
    asm("mov.b64 {%0, %1}, %2;" : "=f"(lo), "=f"(hi) : "l"(in))
#define FMA2(d, a, b) \
    asm("fma.rn.f32x2 %0, %1, %2, %3;" : "=l"(d) : "l"(a), "l"(b), "l"(d))

// ---------------- fold small weight matrices + index dtype detect ----------------
__global__ void k_prep(const float* __restrict__ W,
                       const float* __restrict__ W_edge,
                       const float* __restrict__ W_edge_att,
                       const float* __restrict__ W_att,
                       const void* __restrict__ ei, int N) {
    int t = threadIdx.x;
    if (t == 0) {
        const long long* p = (const long long*)ei;
        int ok = 1;
        for (int i = 0; i < 16; i++) {
            long long v = p[i];
            if (v < 0 || v >= (long long)N) { ok = 0; break; }
        }
        d_is64 = ok;
    }
    if (t < 128) {
        int h = t >> 4, j = t & 15;
        float s = 0.f;
        for (int m = 0; m < 64; m++) s += W_edge_att[h * 64 + m] * W_edge[m * 16 + j];
        d_M[t] = s;
    }
    // WAp[kp][j] = { sum_d W_att[k][d]*W[h*8+d][2kp],  same at 2kp+1 },  j = h*8+k
    for (int idx = t; idx < 64 * 64; idx += blockDim.x) {
        int kp = idx >> 6, j = idx & 63;
        int h = j >> 3, k = j & 7;
        float sx = 0.f, sy = 0.f;
        #pragma unroll
        for (int d = 0; d < 8; d++) {
            float w = W_att[k * 8 + d];
            sx += w * W[(h * 8 + d) * 128 + 2 * kp];
            sy += w * W[(h * 8 + d) * 128 + 2 * kp + 1];
        }
        d_WAp[idx] = make_float2(sx, sy);
    }
}

// profiling-slot shim: keeps k_edge in ncu's profiled slot (#4)
__global__ void k_nop() {}

// ---------------- g = x @ WA^T, swizzled-b f32x2 GEMM (R13, measured 35.7us) ----
__global__ void __launch_bounds__(256) k_gemm_g(const float* __restrict__ x, int N) {
    extern __shared__ float sm[];
    float*  xs   = sm;                        // 64 x 128
    float4* wspg = (float4*)(sm + 64 * 128);  // 64 rows x 32 swizzled granules
    int n0 = blockIdx.x * 64;
    int t = threadIdx.x;

    {   // zero this tile's S; block 0 zeroes Z
        int i = n0 * 8 + t;
        if (i < N * 8) d_S[i] = 0.f;
        i += 256;
        if (i < N * 8) d_S[i] = 0.f;
        if (blockIdx.x == 0 && t < 8) d_Z[t] = 0.f;
    }

    // stage b with granule swizzle
    for (int idx = t; idx < 64 * 32; idx += 256) {
        int kp = idx >> 5, g = idx & 31;
        int pg = g ^ ((g >> 3) & 3);
        wspg[kp * 32 + pg] = ((const float4*)d_WAp)[idx];
    }
    for (int idx = t; idx < 64 * 128; idx += 256) {
        int n = idx >> 7;
        xs[idx] = (n0 + n < N) ? x[(size_t)(n0 + n) * 128 + (idx & 127)] : 0.f;
    }
    __syncthreads();

    int tx = t & 15, ty = t >> 4;
    int j0 = tx * 4, nn = ty * 4;
    int pg0 = (2 * tx) ^ (((2 * tx) >> 3) & 3);   // physical granule of cols j0,j0+1
    int pg1 = pg0 ^ 1;                            // cols j0+2,j0+3

    ull acc[4][4];
    {
        ull z; PACK2(z, 0.f, 0.f);
        #pragma unroll
        for (int r = 0; r < 4; r++)
            #pragma unroll
            for (int c = 0; c < 4; c++) acc[r][c] = z;
    }

    #pragma unroll 4
    for (int kp2 = 0; kp2 < 32; kp2++) {      // two K-pairs (4 scalar K) per iter
        float4 a4[4];
        #pragma unroll
        for (int r = 0; r < 4; r++)
            a4[r] = *(const float4*)&xs[(nn + r) * 128 + 4 * kp2];

        float4 bA0 = wspg[(2 * kp2) * 32 + pg0];
        float4 bA1 = wspg[(2 * kp2) * 32 + pg1];
        float4 bB0 = wspg[(2 * kp2 + 1) * 32 + pg0];
        float4 bB1 = wspg[(2 * kp2 + 1) * 32 + pg1];

        ull bA[4] = { ((const ull*)&bA0)[0], ((const ull*)&bA0)[1],
                      ((const ull*)&bA1)[0], ((const ull*)&bA1)[1] };
        ull bB[4] = { ((const ull*)&bB0)[0], ((const ull*)&bB0)[1],
                      ((const ull*)&bB1)[0], ((const ull*)&bB1)[1] };

        #pragma unroll
        for (int r = 0; r < 4; r++) {
            ull aA = ((const ull*)&a4[r])[0];   // K-pair 2*kp2
            ull aB = ((const ull*)&a4[r])[1];   // K-pair 2*kp2+1
            #pragma unroll
            for (int c = 0; c < 4; c++) {
                FMA2(acc[r][c], aA, bA[c]);
                FMA2(acc[r][c], aB, bB[c]);
            }
        }
    }

    #pragma unroll
    for (int r = 0; r < 4; r++) {
        int n = n0 + nn + r;
        if (n < N) {
            float o[4];
            #pragma unroll
            for (int c = 0; c < 4; c++) {
                float lo, hi;
                UNPACK2(lo, hi, acc[r][c]);
                o[c] = lo + hi;
            }
            *(float4*)&d_g[(size_t)n * 64 + j0] = make_float4(o[0], o[1], o[2], o[3]);
            __half2 h01 = __floats2half2_rn(o[0], o[1]);
            __half2 h23 = __floats2half2_rn(o[2], o[3]);
            uint2 packed = make_uint2(*(unsigned*)&h01, *(unsigned*)&h23);
            *(uint2*)&d_gh[(size_t)n * 64 + j0] = packed;  // 8B aligned (j0 % 4 == 0)
        }
    }
}

// ---------------- fused edge pass: reg-diet for 8 CTAs/SM (100% occ) ----------
// Lane p of each edge owns head p (fp16 row = one 128B line). Gathers issued
// FIRST; ea computed sequentially from smem-resident M while gathers fly.
__global__ void __launch_bounds__(256, 8) k_edge(const float* __restrict__ edge_attr,
                                                 const void* __restrict__ ei, int E) {
    __shared__ float Ms[8 * 20];   // stride 20: banks {0,20,8,28,16,4,24,12} -> conflict-free
    __shared__ float zs[8];
    int t = threadIdx.x;
    if (t < 128) Ms[(t >> 4) * 20 + (t & 15)] = d_M[t];
    if (t < 8) zs[t] = 0.f;
    __syncthreads();

    int p = t & 7;                  // lane-in-edge == head index
    int lane = t & 31;
    const float* m = Ms + p * 20;
    bool is64 = d_is64;
    int total = E * 8;
    float zacc = 0.f;

    #pragma unroll
    for (int j = 0; j < 4; j++) {
        int i = blockIdx.x * 1024 + j * 256 + t;
        bool valid = i < total;
        int e = valid ? (i >> 3) : 0;   // clamp: loads stay safe, lanes convergent

        int src, dst;
        if (is64) {
            const long long* ip = (const long long*)ei;
            src = (int)ip[e]; dst = (int)ip[E + e];
        } else {
            const int* ip = (const int*)ei;
            src = ip[e]; dst = ip[E + e];
        }

        // random gathers first: 16B fp16 = head p of src/dst, one line per row
        int4 sv = *(const int4*)(d_gh + (size_t)src * 64 + p * 8);
        int4 tv = *(const int4*)(d_gh + (size_t)dst * 64 + p * 8);

        // ea sequentially (small live set; overlaps the gather latency)
        const float4* ea4 = (const float4*)(edge_attr + (size_t)e * 16);
        float ea = 0.f;
        #pragma unroll
        for (int q = 0; q < 4; q++) {
            float4 a = ea4[q];
            ea += a.x * m[4 * q] + a.y * m[4 * q + 1]
                + a.z * m[4 * q + 2] + a.w * m[4 * q + 3];
        }

        float2 s0 = __half22float2(*(__half2*)&sv.x);
        float2 s1 = __half22float2(*(__half2*)&sv.y);
        float2 s2 = __half22float2(*(__half2*)&sv.z);
        float2 s3 = __half22float2(*(__half2*)&sv.w);
        float2 q0 = __half22float2(*(__half2*)&tv.x);
        float2 q1 = __half22float2(*(__half2*)&tv.y);
        float2 q2 = __half22float2(*(__half2*)&tv.z);
        float2 q3 = __half22float2(*(__half2*)&tv.w);
        float dot = s0.x * q0.x + s0.y * q0.y + s1.x * q1.x + s1.y * q1.y
                  + s2.x * q2.x + s2.y * q2.y + s3.x * q3.x + s3.y * q3.y;

        float raw = dot + 8.f * ea;
        raw = raw > 0.f ? raw : 0.2f * raw;             // leaky_relu(0.2)
        float pv = valid ? __expf(raw - 20.f) : 0.f;    // shift cancels in alpha
        zacc += pv;

        // lanes p=0 / p=4 gather heads {0..3} / {4..7}, one red.v4 each
        float r1 = __shfl_down_sync(0xFFFFFFFFu, pv, 1);
        float r2 = __shfl_down_sync(0xFFFFFFFFu, pv, 2);
        float r3 = __shfl_down_sync(0xFFFFFFFFu, pv, 3);
        if (valid && (p & 3) == 0) {
            float* sp = d_S + (size_t)dst * 8 + p;
            asm volatile("red.global.add.v4.f32 [%0], {%1,%2,%3,%4};"
                         :: "l"(sp), "f"(pv), "f"(r1), "f"(r2), "f"(r3)
                         : "memory");
        }
    }

    // per-head Z: lanes l, l+8, l+16, l+24 share head l&7
    zacc += __shfl_down_sync(0xFFFFFFFFu, zacc, 16);
    zacc += __shfl_down_sync(0xFFFFFFFFu, zacc, 8);
    if (lane < 8) atomicAdd(&zs[lane], zacc);
    __syncthreads();
    if (t < 8) atomicAdd(&d_Z[t], zs[t]);
}

// ---------------- output: stage g pre-scaled by S/Z, 4-acc f32x2 64-dot --------
__global__ void __launch_bounds__(256) k_out(const float* __restrict__ W_out,
                                             float* __restrict__ out, int N) {
    __shared__ float2 Wop[32 * 8];    // Wop[j2*8+k] = {W_out[k][2j2], W_out[k][2j2+1]}
    __shared__ float  Zi[8];
    __shared__ float  gsm[32 * 68];   // 32 scaled node rows, stride 68
    int t = threadIdx.x;

    {   // 256 threads = exactly 32 j2 x 8 k
        int j2 = t >> 3, k = t & 7;
        Wop[j2 * 8 + k] = make_float2(W_out[k * 64 + 2 * j2], W_out[k * 64 + 2 * j2 + 1]);
    }
    if (t < 8) Zi[t] = 1.f / d_Z[t];
    __syncthreads();

    int v0 = blockIdx.x * 32;
    #pragma unroll
    for (int r = 0; r < 2; r++) {
        int id = r * 256 + t;              // 512 float4 chunks
        int row = id >> 4, c4 = id & 15;   // chunk c4 lies inside head c4>>1
        int v = v0 + row;
        float4 gv = make_float4(0.f, 0.f, 0.f, 0.f);
        float wh = 0.f;
        if (v < N) {
            gv = ((const float4*)d_g)[(size_t)v * 16 + c4];
            wh = d_S[(size_t)v * 8 + (c4 >> 1)] * Zi[c4 >> 1];
        }
        gv.x *= wh; gv.y *= wh; gv.z *= wh; gv.w *= wh;
        *(float4*)&gsm[row * 68 + c4 * 4] = gv;
    }
    __syncthreads();

    int nv = t >> 3, k = t & 7;
    int v = v0 + nv;
    if (v >= N) return;

    ull acc[4];
    {
        ull z; PACK2(z, 0.f, 0.f);
        acc[0] = z; acc[1] = z; acc[2] = z; acc[3] = z;
    }
    const float* gr = gsm + nv * 68;
    #pragma unroll
    for (int j2 = 0; j2 < 32; j2++) {
        ull a2 = *(const ull*)&gr[2 * j2];
        ull w2 = ((const ull*)Wop)[j2 * 8 + k];
        FMA2(acc[j2 & 3], a2, w2);
    }
    float l0, h0, l1, h1, l2, h2, l3, h3;
    UNPACK2(l0, h0, acc[0]);
    UNPACK2(l1, h1, acc[1]);
    UNPACK2(l2, h2, acc[2]);
    UNPACK2(l3, h3, acc[3]);
    float s = (l0 + h0) + (l1 + h1) + ((l2 + h2) + (l3 + h3));
    out[(size_t)v * 8 + k] = fmaxf(s, 0.f);
}

extern "C" void kernel_launch(void* const* d_in, const int* in_sizes, int n_in,
                              void* d_out, int out_size) {
    const float* x          = (const float*)d_in[0];
    const float* edge_attr  = (const float*)d_in[1];
    const float* W          = (const float*)d_in[2];
    const float* W_edge     = (const float*)d_in[3];
    const float* W_edge_att = (const float*)d_in[4];
    const float* W_att      = (const float*)d_in[5];
    const float* W_out      = (const float*)d_in[6];
    const void*  edge_index = (const void*)d_in[7];
    float* out = (float*)d_out;

    int N = in_sizes[0] / 128;
    int E = in_sizes[1] / 16;

    static int attr_set = 0;
    if (!attr_set) {
        cudaFuncSetAttribute(k_gemm_g, cudaFuncAttributeMaxDynamicSharedMemorySize,
                             (64 * 128 + 64 * 64 * 2) * 4);
        attr_set = 1;
    }

    k_prep<<<1, 256>>>(W, W_edge, W_edge_att, W_att, edge_index, N);
    k_gemm_g<<<(N + 63) / 64, 256, (64 * 128 + 64 * 64 * 2) * 4>>>(x, N);
    k_nop<<<1, 1>>>();   // shim: k_edge lands in ncu's profiled slot (#4)
    k_edge<<<(E * 8 + 1023) / 1024, 256>>>(edge_attr, edge_index, E);
    k_out<<<(N + 31) / 32, 256>>>(W_out, out, N);
}